// round 1
// baseline (speedup 1.0000x reference)
#include <cuda_runtime.h>
#include <cuda_bf16.h>
#include <cstdint>

// Problem dims
#define BB   64
#define SS   1024
#define II   256
#define HH   256
#define G3   768   // 3*H

// Scratch for input-side gate projections: [B*S, 768] fp32 = 201MB
__device__ float g_xg[(size_t)BB * SS * G3];

// ---------------------------------------------------------------------------
// GEMM: g_xg[r, g] = sum_i X[r*lda + i] * W[g*256 + i] + bias[g]
// M = B*S = 65536 rows, N = 768, K = 256.  BM=128, BN=64, BK=16, 256 threads.
// ---------------------------------------------------------------------------
__global__ void __launch_bounds__(256)
gemm_xg_kernel(const float* __restrict__ X, long lda,
               const float* __restrict__ W, const float* __restrict__ bias)
{
    __shared__ float As[16][132];  // [k][m], padded
    __shared__ float Bs[16][68];   // [k][n], padded

    const int t   = threadIdx.x;
    const int tx  = t & 15;        // n direction, 4 cols each
    const int ty  = t >> 4;        // m direction, 8 rows each
    const int r0  = blockIdx.y * 128;
    const int g0  = blockIdx.x * 64;

    const int arow = t >> 2;            // 0..63
    const int ak   = (t & 3) * 4;       // 0,4,8,12

    float acc[8][4];
#pragma unroll
    for (int i = 0; i < 8; i++)
#pragma unroll
        for (int j = 0; j < 4; j++) acc[i][j] = 0.f;

    for (int kt = 0; kt < 16; kt++) {
        const int k0 = kt * 16;
        // load A tile (128 x 16), transposed into As[k][m]
        float4 a0 = *reinterpret_cast<const float4*>(X + (size_t)(r0 + arow) * lda + k0 + ak);
        float4 a1 = *reinterpret_cast<const float4*>(X + (size_t)(r0 + arow + 64) * lda + k0 + ak);
        As[ak + 0][arow] = a0.x; As[ak + 1][arow] = a0.y;
        As[ak + 2][arow] = a0.z; As[ak + 3][arow] = a0.w;
        As[ak + 0][arow + 64] = a1.x; As[ak + 1][arow + 64] = a1.y;
        As[ak + 2][arow + 64] = a1.z; As[ak + 3][arow + 64] = a1.w;
        // load B tile (64 x 16) from W, transposed into Bs[k][n]
        float4 bv = *reinterpret_cast<const float4*>(W + (size_t)(g0 + arow) * 256 + k0 + ak);
        Bs[ak + 0][arow] = bv.x; Bs[ak + 1][arow] = bv.y;
        Bs[ak + 2][arow] = bv.z; Bs[ak + 3][arow] = bv.w;
        __syncthreads();

#pragma unroll
        for (int kk = 0; kk < 16; kk++) {
            float4 av0 = *reinterpret_cast<const float4*>(&As[kk][ty * 8]);
            float4 av1 = *reinterpret_cast<const float4*>(&As[kk][ty * 8 + 4]);
            float4 bv4 = *reinterpret_cast<const float4*>(&Bs[kk][tx * 4]);
            float a[8] = {av0.x, av0.y, av0.z, av0.w, av1.x, av1.y, av1.z, av1.w};
            float b[4] = {bv4.x, bv4.y, bv4.z, bv4.w};
#pragma unroll
            for (int i = 0; i < 8; i++)
#pragma unroll
                for (int j = 0; j < 4; j++)
                    acc[i][j] = fmaf(a[i], b[j], acc[i][j]);
        }
        __syncthreads();
    }

    float4 b4 = *reinterpret_cast<const float4*>(bias + g0 + tx * 4);
#pragma unroll
    for (int i = 0; i < 8; i++) {
        size_t row = (size_t)(r0 + ty * 8 + i);
        float4 v;
        v.x = acc[i][0] + b4.x; v.y = acc[i][1] + b4.y;
        v.z = acc[i][2] + b4.z; v.w = acc[i][3] + b4.w;
        *reinterpret_cast<float4*>(&g_xg[row * G3 + g0 + tx * 4]) = v;
    }
}

// ---------------------------------------------------------------------------
// Persistent GRU scan. Cluster of 4 CTAs per 2 batch elements.
// CTA rank c owns hidden units [64c, 64c+64). 512 threads: 8 threads/unit,
// each thread holds 3 gates x 32 W_hh weights in registers (96 fp32 regs).
// Hidden state (2 batches x 256) replicated in every CTA's smem, double
// buffered; unit leaders broadcast h_new via st.shared::cluster; one
// barrier.cluster per timestep.
// ---------------------------------------------------------------------------
__global__ void __cluster_dims__(4, 1, 1) __launch_bounds__(512, 1)
gru_scan_kernel(const float* __restrict__ Whh,   // [768,256]
                const float* __restrict__ bhh,   // [768]
                float* __restrict__ outA, int strideA,
                float* __restrict__ outB, int strideB) // outB may be null
{
    __shared__ float hbuf[2][2][HH];   // [parity][batch-slot][hidden]

    const int c    = blockIdx.x;                    // cluster rank 0..3
    const int tid  = threadIdx.x;
    const int warp = tid >> 5;
    const int lane = tid & 31;
    const int jg   = c * 64 + warp * 4 + (lane >> 3);  // global hidden unit 0..255
    const int k0   = (lane & 7) * 32;                  // k-chunk start
    const bool leader = (lane & 7) == 0;
    const int b0   = blockIdx.y * 2;

    // -- load recurrent weights into registers (once) --
    float wr[32], wz[32], wn[32];
    {
        const float4* pr = reinterpret_cast<const float4*>(Whh + (size_t)(jg) * HH + k0);
        const float4* pz = reinterpret_cast<const float4*>(Whh + (size_t)(256 + jg) * HH + k0);
        const float4* pn = reinterpret_cast<const float4*>(Whh + (size_t)(512 + jg) * HH + k0);
#pragma unroll
        for (int i = 0; i < 8; i++) {
            float4 a = pr[i]; wr[4*i]=a.x; wr[4*i+1]=a.y; wr[4*i+2]=a.z; wr[4*i+3]=a.w;
            float4 b = pz[i]; wz[4*i]=b.x; wz[4*i+1]=b.y; wz[4*i+2]=b.z; wz[4*i+3]=b.w;
            float4 d = pn[i]; wn[4*i]=d.x; wn[4*i+1]=d.y; wn[4*i+2]=d.z; wn[4*i+3]=d.w;
        }
    }
    float bh_r = 0.f, bh_z = 0.f, bh_n = 0.f;
    if (leader) { bh_r = bhh[jg]; bh_z = bhh[256 + jg]; bh_n = bhh[512 + jg]; }

    // zero initial hidden state (parity 0)
    ((float*)hbuf[0])[tid] = 0.f;

    // prefetch xg for t = 0 (leaders only)
    float xpr[2], xpz[2], xpn[2];
    if (leader) {
#pragma unroll
        for (int sb = 0; sb < 2; sb++) {
            size_t base = ((size_t)(b0 + sb) * SS) * G3;
            xpr[sb] = __ldg(&g_xg[base + jg]);
            xpz[sb] = __ldg(&g_xg[base + 256 + jg]);
            xpn[sb] = __ldg(&g_xg[base + 512 + jg]);
        }
    }

    asm volatile("barrier.cluster.arrive.aligned;" ::: "memory");
    asm volatile("barrier.cluster.wait.aligned;"   ::: "memory");

    uint32_t hb_base = (uint32_t)__cvta_generic_to_shared(hbuf);

    for (int t = 0; t < SS; t++) {
        const int p = t & 1;
        float xr[2], xz[2], xn[2];
        if (leader) {
#pragma unroll
            for (int sb = 0; sb < 2; sb++) { xr[sb]=xpr[sb]; xz[sb]=xpz[sb]; xn[sb]=xpn[sb]; }
            const int tn = (t + 1 < SS) ? t + 1 : t;
#pragma unroll
            for (int sb = 0; sb < 2; sb++) {
                size_t base = ((size_t)(b0 + sb) * SS + tn) * G3;
                xpr[sb] = __ldg(&g_xg[base + jg]);
                xpz[sb] = __ldg(&g_xg[base + 256 + jg]);
                xpn[sb] = __ldg(&g_xg[base + 512 + jg]);
            }
        }

#pragma unroll
        for (int sb = 0; sb < 2; sb++) {
            const float* hp = &hbuf[p][sb][k0];
            float aR = 0.f, aZ = 0.f, aN = 0.f;
#pragma unroll
            for (int i = 0; i < 32; i++) {
                float hv = hp[i];
                aR = fmaf(wr[i], hv, aR);
                aZ = fmaf(wz[i], hv, aZ);
                aN = fmaf(wn[i], hv, aN);
            }
            // reduce across the 8 k-chunk threads of this unit
#pragma unroll
            for (int d = 4; d; d >>= 1) {
                aR += __shfl_down_sync(0xffffffffu, aR, d);
                aZ += __shfl_down_sync(0xffffffffu, aZ, d);
                aN += __shfl_down_sync(0xffffffffu, aN, d);
            }
            if (leader) {
                float r = 1.f / (1.f + __expf(-(xr[sb] + aR + bh_r)));
                float z = 1.f / (1.f + __expf(-(xz[sb] + aZ + bh_z)));
                float n = tanhf(xn[sb] + r * (aN + bh_n));
                float hold = hbuf[p][sb][jg];
                float hnew = (1.f - z) * n + z * hold;

                size_t row = (size_t)(b0 + sb) * SS + t;
                outA[row * strideA + jg] = hnew;
                if (outB) outB[row * strideB + jg] = hnew;

                // broadcast h_new into all 4 CTAs' next-parity buffer
                uint32_t laddr = hb_base + (uint32_t)((((p ^ 1) * 2 + sb) * HH + jg) << 2);
#pragma unroll
                for (int rk = 0; rk < 4; rk++) {
                    uint32_t rem;
                    asm volatile("mapa.shared::cluster.u32 %0, %1, %2;"
                                 : "=r"(rem) : "r"(laddr), "r"(rk));
                    asm volatile("st.shared::cluster.f32 [%0], %1;"
                                 :: "r"(rem), "f"(hnew) : "memory");
                }
            }
        }
        asm volatile("barrier.cluster.arrive.aligned;" ::: "memory");
        asm volatile("barrier.cluster.wait.aligned;"   ::: "memory");
    }
}

// ---------------------------------------------------------------------------
// kernel_launch
// ---------------------------------------------------------------------------
extern "C" void kernel_launch(void* const* d_in, const int* in_sizes, int n_in,
                              void* d_out, int out_size)
{
    (void)in_sizes; (void)n_in; (void)out_size;
    const float* inputs = (const float*)d_in[0];
    const float* W_ih0  = (const float*)d_in[1];
    const float* W_hh0  = (const float*)d_in[2];
    const float* b_ih0  = (const float*)d_in[3];
    const float* b_hh0  = (const float*)d_in[4];
    const float* W_ih1  = (const float*)d_in[5];
    const float* W_hh1  = (const float*)d_in[6];
    const float* b_ih1  = (const float*)d_in[7];
    const float* b_hh1  = (const float*)d_in[8];

    float* out    = (float*)d_out;
    float* h2     = out;                              // [B,S,H]
    float* concat = out + (size_t)BB * SS * HH;       // [B,S,2H]: [:,:,0:H]=h1, [:,:,H:2H]=h2

    dim3 gemm_grid(G3 / 64, (BB * SS) / 128);
    dim3 scan_grid(4, BB / 2);

    // Layer 0: xg0 = inputs @ W_ih0^T + b_ih0 ; scan -> h1 into concat[:, :, 0:256]
    gemm_xg_kernel<<<gemm_grid, 256>>>(inputs, (long)II, W_ih0, b_ih0);
    gru_scan_kernel<<<scan_grid, 512>>>(W_hh0, b_hh0, concat, 2 * HH, nullptr, 0);

    // Layer 1: xg1 = h1 @ W_ih1^T + b_ih1 (h1 read from concat, lda = 512)
    gemm_xg_kernel<<<gemm_grid, 256>>>(concat, (long)(2 * HH), W_ih1, b_ih1);
    // scan -> h2 into concat[:, :, 256:512] AND into h2 output
    gru_scan_kernel<<<scan_grid, 512>>>(W_hh1, b_hh1, concat + HH, 2 * HH, h2, HH);
}

// round 2
// speedup vs baseline: 1.1848x; 1.1848x over previous
#include <cuda_runtime.h>
#include <cstdint>

#define BB   64
#define SS   1024
#define II   256
#define HH   256
#define G3   768

typedef unsigned long long u64;

// Scratch for input-side gate projections: [B*S, 768] fp32
__device__ float g_xg[(size_t)BB * SS * G3];

__device__ __forceinline__ u64 ffma2(u64 a, u64 b, u64 c) {
    u64 d; asm("fma.rn.f32x2 %0, %1, %2, %3;" : "=l"(d) : "l"(a), "l"(b), "l"(c)); return d;
}
__device__ __forceinline__ float rcpa(float x) {
    float y; asm("rcp.approx.f32 %0, %1;" : "=f"(y) : "f"(x)); return y;
}
__device__ __forceinline__ float2 unpack2(u64 v) {
    float2 f; asm("mov.b64 {%0, %1}, %2;" : "=f"(f.x), "=f"(f.y) : "l"(v)); return f;
}
__device__ __forceinline__ u64 packdup(float x) {
    u64 v; asm("mov.b64 %0, {%1, %2};" : "=l"(v) : "f"(x), "f"(x)); return v;
}
__device__ __forceinline__ uint32_t smem_u32(const void* p) {
    return (uint32_t)__cvta_generic_to_shared(p);
}

// ---------------------------------------------------------------------------
// GEMM with f32x2 packed FMA: g_xg[r,g] = sum_i X[r*lda+i]*W[g*256+i] + bias[g]
// M=65536, N=768, K=256. BM=128, BN=64, BK=16, 256 threads.
// acc packed over adjacent m rows.
// ---------------------------------------------------------------------------
__global__ void __launch_bounds__(256)
gemm_xg_kernel(const float* __restrict__ X, long lda,
               const float* __restrict__ W, const float* __restrict__ bias)
{
    __shared__ alignas(16) float As[16][132];  // [k][m]
    __shared__ alignas(16) float Bs[16][68];   // [k][n]

    const int t   = threadIdx.x;
    const int tx  = t & 15;        // n dir, 4 cols
    const int ty  = t >> 4;        // m dir, 8 rows (4 m-pairs)
    const int r0  = blockIdx.y * 128;
    const int g0  = blockIdx.x * 64;

    const int arow = t >> 2;
    const int ak   = (t & 3) * 4;

    u64 acc2[4][4];
#pragma unroll
    for (int i = 0; i < 4; i++)
#pragma unroll
        for (int j = 0; j < 4; j++) acc2[i][j] = 0ull;

    for (int kt = 0; kt < 16; kt++) {
        const int k0 = kt * 16;
        float4 a0 = *reinterpret_cast<const float4*>(X + (size_t)(r0 + arow) * lda + k0 + ak);
        float4 a1 = *reinterpret_cast<const float4*>(X + (size_t)(r0 + arow + 64) * lda + k0 + ak);
        As[ak + 0][arow] = a0.x; As[ak + 1][arow] = a0.y;
        As[ak + 2][arow] = a0.z; As[ak + 3][arow] = a0.w;
        As[ak + 0][arow + 64] = a1.x; As[ak + 1][arow + 64] = a1.y;
        As[ak + 2][arow + 64] = a1.z; As[ak + 3][arow + 64] = a1.w;
        float4 bv = *reinterpret_cast<const float4*>(W + (size_t)(g0 + arow) * 256 + k0 + ak);
        Bs[ak + 0][arow] = bv.x; Bs[ak + 1][arow] = bv.y;
        Bs[ak + 2][arow] = bv.z; Bs[ak + 3][arow] = bv.w;
        __syncthreads();

#pragma unroll
        for (int kk = 0; kk < 16; kk++) {
            const u64* ap = reinterpret_cast<const u64*>(&As[kk][ty * 8]);
            u64 pa0 = ap[0], pa1 = ap[1], pa2 = ap[2], pa3 = ap[3];
            float4 bv4 = *reinterpret_cast<const float4*>(&Bs[kk][tx * 4]);
            u64 pb0 = packdup(bv4.x), pb1 = packdup(bv4.y);
            u64 pb2 = packdup(bv4.z), pb3 = packdup(bv4.w);
            acc2[0][0] = ffma2(pa0, pb0, acc2[0][0]);
            acc2[0][1] = ffma2(pa0, pb1, acc2[0][1]);
            acc2[0][2] = ffma2(pa0, pb2, acc2[0][2]);
            acc2[0][3] = ffma2(pa0, pb3, acc2[0][3]);
            acc2[1][0] = ffma2(pa1, pb0, acc2[1][0]);
            acc2[1][1] = ffma2(pa1, pb1, acc2[1][1]);
            acc2[1][2] = ffma2(pa1, pb2, acc2[1][2]);
            acc2[1][3] = ffma2(pa1, pb3, acc2[1][3]);
            acc2[2][0] = ffma2(pa2, pb0, acc2[2][0]);
            acc2[2][1] = ffma2(pa2, pb1, acc2[2][1]);
            acc2[2][2] = ffma2(pa2, pb2, acc2[2][2]);
            acc2[2][3] = ffma2(pa2, pb3, acc2[2][3]);
            acc2[3][0] = ffma2(pa3, pb0, acc2[3][0]);
            acc2[3][1] = ffma2(pa3, pb1, acc2[3][1]);
            acc2[3][2] = ffma2(pa3, pb2, acc2[3][2]);
            acc2[3][3] = ffma2(pa3, pb3, acc2[3][3]);
        }
        __syncthreads();
    }

    float4 b4 = *reinterpret_cast<const float4*>(bias + g0 + tx * 4);
#pragma unroll
    for (int i = 0; i < 4; i++) {
        float2 c0 = unpack2(acc2[i][0]), c1 = unpack2(acc2[i][1]);
        float2 c2 = unpack2(acc2[i][2]), c3 = unpack2(acc2[i][3]);
        size_t row0 = (size_t)(r0 + ty * 8 + 2 * i);
        float4 v0, v1;
        v0.x = c0.x + b4.x; v0.y = c1.x + b4.y; v0.z = c2.x + b4.z; v0.w = c3.x + b4.w;
        v1.x = c0.y + b4.x; v1.y = c1.y + b4.y; v1.z = c2.y + b4.z; v1.w = c3.y + b4.w;
        *reinterpret_cast<float4*>(&g_xg[row0 * G3 + g0 + tx * 4]) = v0;
        *reinterpret_cast<float4*>(&g_xg[(row0 + 1) * G3 + g0 + tx * 4]) = v1;
    }
}

// ---------------------------------------------------------------------------
// Persistent GRU scan. Cluster of 4 CTAs per 2 batch elements.
// Weights register-resident as f32x2 pairs. Per-step cross-CTA h exchange via
// st.async + mbarrier complete_tx (double-buffered), replacing cluster.sync.
// ---------------------------------------------------------------------------
__global__ void __cluster_dims__(4, 1, 1) __launch_bounds__(512, 1)
gru_scan_kernel(const float* __restrict__ Whh,   // [768,256]
                const float* __restrict__ bhh,   // [768]
                float* __restrict__ out, int ostride)
{
    __shared__ alignas(16) float hbuf[2][2][HH];  // [slot][batch-slot][hidden]
    __shared__ alignas(16) float stage[2][64];    // [batch-slot][local unit]
    __shared__ alignas(8)  u64   mbars[2];

    const int c    = blockIdx.x;            // cluster rank
    const int tid  = threadIdx.x;
    const int warp = tid >> 5;
    const int lane = tid & 31;
    const int ul   = warp * 4 + (lane >> 3);   // local unit 0..63
    const int jg   = c * 64 + ul;              // global hidden unit
    const int k0   = (lane & 7) * 32;          // k-chunk
    const bool leader = (lane & 7) == 0;
    const int b0   = blockIdx.y * 2;

    // recurrent weights -> registers, packed as (k, k+1) f32 pairs
    u64 wr2[16], wz2[16], wn2[16];
    {
        const u64* pr = reinterpret_cast<const u64*>(Whh + (size_t)jg * HH + k0);
        const u64* pz = reinterpret_cast<const u64*>(Whh + (size_t)(256 + jg) * HH + k0);
        const u64* pq = reinterpret_cast<const u64*>(Whh + (size_t)(512 + jg) * HH + k0);
#pragma unroll
        for (int i = 0; i < 16; i++) { wr2[i] = pr[i]; wz2[i] = pz[i]; wn2[i] = pq[i]; }
    }
    float bhr = 0.f, bhz = 0.f, bhn = 0.f;
    if (leader) { bhr = bhh[jg]; bhz = bhh[256 + jg]; bhn = bhh[512 + jg]; }

    ((float*)hbuf)[tid] = 0.0f;   // zero hbuf[0][*][*] (512 floats)
    const uint32_t mb = smem_u32(mbars);
    const uint32_t hb = smem_u32(hbuf);
    if (tid == 0) {
        asm volatile("mbarrier.init.shared.b64 [%0], 1;" :: "r"(mb)     : "memory");
        asm volatile("mbarrier.init.shared.b64 [%0], 1;" :: "r"(mb + 8) : "memory");
    }
    __syncthreads();
    asm volatile("barrier.cluster.arrive.aligned;" ::: "memory");
    asm volatile("barrier.cluster.wait.aligned;"   ::: "memory");

    // prefetch xg for t=0 (leaders)
    float xpr[2], xpz[2], xpn[2];
    if (leader) {
#pragma unroll
        for (int sb = 0; sb < 2; sb++) {
            size_t base = ((size_t)(b0 + sb) * SS) * G3;
            xpr[sb] = __ldg(&g_xg[base + jg]);
            xpz[sb] = __ldg(&g_xg[base + 256 + jg]);
            xpn[sb] = __ldg(&g_xg[base + 512 + jg]);
        }
    }

    int ph0 = 0, ph1 = 0;

    for (int t = 0; t < SS; t++) {
        const int p = t & 1, pq = p ^ 1;
        if (tid == 0) {
            // expect incoming step-(t+1) data: 4 CTAs x 512B
            asm volatile("mbarrier.arrive.expect_tx.shared.b64 _, [%0], %1;"
                         :: "r"(mb + pq * 8), "r"(2048u) : "memory");
        }
        float xr[2], xz[2], xn[2];
        if (leader) {
#pragma unroll
            for (int sb = 0; sb < 2; sb++) { xr[sb]=xpr[sb]; xz[sb]=xpz[sb]; xn[sb]=xpn[sb]; }
            const int tn = (t + 1 < SS) ? t + 1 : t;
#pragma unroll
            for (int sb = 0; sb < 2; sb++) {
                size_t base = ((size_t)(b0 + sb) * SS + tn) * G3;
                xpr[sb] = __ldg(&g_xg[base + jg]);
                xpz[sb] = __ldg(&g_xg[base + 256 + jg]);
                xpn[sb] = __ldg(&g_xg[base + 512 + jg]);
            }
        }

#pragma unroll
        for (int sb = 0; sb < 2; sb++) {
            const u64* hp = reinterpret_cast<const u64*>(&hbuf[p][sb][k0]);
            u64 aR = 0ull, aZ = 0ull, aN = 0ull;
#pragma unroll
            for (int i = 0; i < 16; i++) {
                u64 hv = hp[i];
                aR = ffma2(wr2[i], hv, aR);
                aZ = ffma2(wz2[i], hv, aZ);
                aN = ffma2(wn2[i], hv, aN);
            }
            float2 fR = unpack2(aR), fZ = unpack2(aZ), fN = unpack2(aN);
            float sR = fR.x + fR.y, sZ = fZ.x + fZ.y, sN = fN.x + fN.y;
#pragma unroll
            for (int d = 4; d; d >>= 1) {
                sR += __shfl_down_sync(0xffffffffu, sR, d);
                sZ += __shfl_down_sync(0xffffffffu, sZ, d);
                sN += __shfl_down_sync(0xffffffffu, sN, d);
            }
            if (leader) {
                float er = __expf(-(xr[sb] + sR + bhr));
                float r  = rcpa(1.f + er);
                float ez = __expf(-(xz[sb] + sZ + bhz));
                float z  = rcpa(1.f + ez);
                float na = xn[sb] + r * (sN + bhn);
                float en = __expf(-2.f * na);
                float n  = (1.f - en) * rcpa(1.f + en);
                float hold = hbuf[p][sb][jg];
                float hnew = n + z * (hold - n);
                out[((size_t)(b0 + sb) * SS + t) * ostride + jg] = hnew;
                stage[sb][ul] = hnew;
            }
        }
        __syncthreads();

        if (tid < 64) {
            const int sb = tid >> 5, j = tid & 31;
            u64 v = *reinterpret_cast<const u64*>(&stage[sb][2 * j]);
            uint32_t loff = hb + (uint32_t)((((pq * 2 + sb) * HH) + c * 64 + 2 * j) * 4);
            uint32_t moff = mb + (uint32_t)(pq * 8);
#pragma unroll
            for (int r = 0; r < 4; r++) {
                uint32_t rh, rm;
                asm volatile("mapa.shared::cluster.u32 %0, %1, %2;" : "=r"(rh) : "r"(loff), "r"(r));
                asm volatile("mapa.shared::cluster.u32 %0, %1, %2;" : "=r"(rm) : "r"(moff), "r"(r));
                asm volatile("st.async.shared::cluster.mbarrier::complete_tx::bytes.b64 [%0], %1, [%2];"
                             :: "r"(rh), "l"(v), "r"(rm) : "memory");
            }
        }

        // wait for step t+1's h to fully land in our hbuf[pq]
        {
            uint32_t maddr = mb + pq * 8;
            uint32_t parity = pq ? ph1 : ph0;
            uint32_t done;
            asm volatile(
                "{\n\t.reg .pred p;\n\t"
                "mbarrier.try_wait.parity.acquire.cta.shared::cta.b64 p, [%1], %2;\n\t"
                "selp.b32 %0, 1, 0, p;\n\t}"
                : "=r"(done) : "r"(maddr), "r"(parity) : "memory");
            if (!done) {
                asm volatile(
                    "{\n\t.reg .pred P1;\n\t"
                    "WL_%=:\n\t"
                    "mbarrier.try_wait.parity.acquire.cta.shared::cta.b64 P1, [%0], %1, 0x989680;\n\t"
                    "@P1 bra.uni WD_%=;\n\t"
                    "bra.uni WL_%=;\n\t"
                    "WD_%=:\n\t}"
                    :: "r"(maddr), "r"(parity) : "memory");
            }
            if (pq) ph1 ^= 1; else ph0 ^= 1;
        }
    }
}

// ---------------------------------------------------------------------------
// h2 = concat[:, :, 256:512]  (vectorized copy)
// ---------------------------------------------------------------------------
__global__ void __launch_bounds__(256)
copy_h2_kernel(const float4* __restrict__ src, float4* __restrict__ dst)
{
    size_t i = (size_t)blockIdx.x * blockDim.x + threadIdx.x;  // 0 .. 64*1024*64
    size_t row = i >> 6;
    int col = (int)(i & 63);
    dst[row * 64 + col] = src[row * 128 + 64 + col];
}

// ---------------------------------------------------------------------------
extern "C" void kernel_launch(void* const* d_in, const int* in_sizes, int n_in,
                              void* d_out, int out_size)
{
    (void)in_sizes; (void)n_in; (void)out_size;
    const float* inputs = (const float*)d_in[0];
    const float* W_ih0  = (const float*)d_in[1];
    const float* W_hh0  = (const float*)d_in[2];
    const float* b_ih0  = (const float*)d_in[3];
    const float* b_hh0  = (const float*)d_in[4];
    const float* W_ih1  = (const float*)d_in[5];
    const float* W_hh1  = (const float*)d_in[6];
    const float* b_ih1  = (const float*)d_in[7];
    const float* b_hh1  = (const float*)d_in[8];

    float* out    = (float*)d_out;
    float* h2     = out;                               // [B,S,H]
    float* concat = out + (size_t)BB * SS * HH;        // [B,S,2H]

    dim3 gemm_grid(G3 / 64, (BB * SS) / 128);
    dim3 scan_grid(4, BB / 2);

    // Layer 0
    gemm_xg_kernel<<<gemm_grid, 256>>>(inputs, (long)II, W_ih0, b_ih0);
    gru_scan_kernel<<<scan_grid, 512>>>(W_hh0, b_hh0, concat, 2 * HH);

    // Layer 1 (reads h1 from concat, lda = 512)
    gemm_xg_kernel<<<gemm_grid, 256>>>(concat, (long)(2 * HH), W_ih1, b_ih1);
    gru_scan_kernel<<<scan_grid, 512>>>(W_hh1, b_hh1, concat + HH, 2 * HH);

    // h2 output = concat[:, :, 256:512]
    copy_h2_kernel<<<16384, 256>>>((const float4*)concat, (float4*)h2);
}

// round 4
// speedup vs baseline: 3.1651x; 2.6714x over previous
#include <cuda_runtime.h>
#include <cstdint>

#define BB   64
#define SS   1024
#define II   256
#define HH   256
#define G3   768
#define CPAD 36   // padded chunk stride: 32 data + 4 pad floats

typedef unsigned long long u64;

// Scratch for input-side gate projections: [B*S, 768] fp32
__device__ float g_xg[(size_t)BB * SS * G3];

__device__ __forceinline__ u64 ffma2(u64 a, u64 b, u64 c) {
    u64 d; asm("fma.rn.f32x2 %0, %1, %2, %3;" : "=l"(d) : "l"(a), "l"(b), "l"(c)); return d;
}
__device__ __forceinline__ float rcpa(float x) {
    float y; asm("rcp.approx.f32 %0, %1;" : "=f"(y) : "f"(x)); return y;
}
__device__ __forceinline__ float2 unpack2(u64 v) {
    float2 f; asm("mov.b64 {%0, %1}, %2;" : "=f"(f.x), "=f"(f.y) : "l"(v)); return f;
}
__device__ __forceinline__ u64 packdup(float x) {
    u64 v; asm("mov.b64 %0, {%1, %2};" : "=l"(v) : "f"(x), "f"(x)); return v;
}
__device__ __forceinline__ uint32_t smem_u32(const void* p) {
    return (uint32_t)__cvta_generic_to_shared(p);
}

// ---------------------------------------------------------------------------
// GEMM with f32x2 packed FMA: g_xg[r,g] = sum_i X[r*lda+i]*W[g*256+i] + bias[g]
// M=65536, N=768, K=256. BM=128, BN=64, BK=16, 256 threads.  (unchanged, passing)
// ---------------------------------------------------------------------------
__global__ void __launch_bounds__(256)
gemm_xg_kernel(const float* __restrict__ X, long lda,
               const float* __restrict__ W, const float* __restrict__ bias)
{
    __shared__ alignas(16) float As[16][132];  // [k][m]
    __shared__ alignas(16) float Bs[16][68];   // [k][n]

    const int t   = threadIdx.x;
    const int tx  = t & 15;
    const int ty  = t >> 4;
    const int r0  = blockIdx.y * 128;
    const int g0  = blockIdx.x * 64;

    const int arow = t >> 2;
    const int ak   = (t & 3) * 4;

    u64 acc2[4][4];
#pragma unroll
    for (int i = 0; i < 4; i++)
#pragma unroll
        for (int j = 0; j < 4; j++) acc2[i][j] = 0ull;

    for (int kt = 0; kt < 16; kt++) {
        const int k0 = kt * 16;
        float4 a0 = *reinterpret_cast<const float4*>(X + (size_t)(r0 + arow) * lda + k0 + ak);
        float4 a1 = *reinterpret_cast<const float4*>(X + (size_t)(r0 + arow + 64) * lda + k0 + ak);
        As[ak + 0][arow] = a0.x; As[ak + 1][arow] = a0.y;
        As[ak + 2][arow] = a0.z; As[ak + 3][arow] = a0.w;
        As[ak + 0][arow + 64] = a1.x; As[ak + 1][arow + 64] = a1.y;
        As[ak + 2][arow + 64] = a1.z; As[ak + 3][arow + 64] = a1.w;
        float4 bv = *reinterpret_cast<const float4*>(W + (size_t)(g0 + arow) * 256 + k0 + ak);
        Bs[ak + 0][arow] = bv.x; Bs[ak + 1][arow] = bv.y;
        Bs[ak + 2][arow] = bv.z; Bs[ak + 3][arow] = bv.w;
        __syncthreads();

#pragma unroll
        for (int kk = 0; kk < 16; kk++) {
            const u64* ap = reinterpret_cast<const u64*>(&As[kk][ty * 8]);
            u64 pa0 = ap[0], pa1 = ap[1], pa2 = ap[2], pa3 = ap[3];
            float4 bv4 = *reinterpret_cast<const float4*>(&Bs[kk][tx * 4]);
            u64 pb0 = packdup(bv4.x), pb1 = packdup(bv4.y);
            u64 pb2 = packdup(bv4.z), pb3 = packdup(bv4.w);
            acc2[0][0] = ffma2(pa0, pb0, acc2[0][0]);
            acc2[0][1] = ffma2(pa0, pb1, acc2[0][1]);
            acc2[0][2] = ffma2(pa0, pb2, acc2[0][2]);
            acc2[0][3] = ffma2(pa0, pb3, acc2[0][3]);
            acc2[1][0] = ffma2(pa1, pb0, acc2[1][0]);
            acc2[1][1] = ffma2(pa1, pb1, acc2[1][1]);
            acc2[1][2] = ffma2(pa1, pb2, acc2[1][2]);
            acc2[1][3] = ffma2(pa1, pb3, acc2[1][3]);
            acc2[2][0] = ffma2(pa2, pb0, acc2[2][0]);
            acc2[2][1] = ffma2(pa2, pb1, acc2[2][1]);
            acc2[2][2] = ffma2(pa2, pb2, acc2[2][2]);
            acc2[2][3] = ffma2(pa2, pb3, acc2[2][3]);
            acc2[3][0] = ffma2(pa3, pb0, acc2[3][0]);
            acc2[3][1] = ffma2(pa3, pb1, acc2[3][1]);
            acc2[3][2] = ffma2(pa3, pb2, acc2[3][2]);
            acc2[3][3] = ffma2(pa3, pb3, acc2[3][3]);
        }
        __syncthreads();
    }

    float4 b4 = *reinterpret_cast<const float4*>(bias + g0 + tx * 4);
#pragma unroll
    for (int i = 0; i < 4; i++) {
        float2 c0 = unpack2(acc2[i][0]), c1 = unpack2(acc2[i][1]);
        float2 c2 = unpack2(acc2[i][2]), c3 = unpack2(acc2[i][3]);
        size_t row0 = (size_t)(r0 + ty * 8 + 2 * i);
        float4 v0, v1;
        v0.x = c0.x + b4.x; v0.y = c1.x + b4.y; v0.z = c2.x + b4.z; v0.w = c3.x + b4.w;
        v1.x = c0.y + b4.x; v1.y = c1.y + b4.y; v1.z = c2.y + b4.z; v1.w = c3.y + b4.w;
        *reinterpret_cast<float4*>(&g_xg[row0 * G3 + g0 + tx * 4]) = v0;
        *reinterpret_cast<float4*>(&g_xg[(row0 + 1) * G3 + g0 + tx * 4]) = v1;
    }
}

// ---------------------------------------------------------------------------
// Persistent GRU scan. 4-CTA cluster per 2 batch elements, W_hh in registers.
// PADDED hidden-state layout (bank-conflict-free) + round-2's proven st.async
// + complete_tx/expect_tx double-buffered sync.
// ---------------------------------------------------------------------------
__global__ void __cluster_dims__(4, 1, 1) __launch_bounds__(512, 1)
gru_scan_kernel(const float* __restrict__ Whh,   // [768,256]
                const float* __restrict__ bhh,   // [768]
                float* __restrict__ out, int ostride)
{
    // [parity][sb][chunk][CPAD]; h element j lives at [.][sb][j>>5][j&31]
    __shared__ alignas(16) float hbuf[2][2][8][CPAD];
    __shared__ alignas(16) float stage[2][64];    // [sb][local unit]
    __shared__ alignas(8)  u64   mbars[2];

    const int c    = blockIdx.x;               // cluster rank
    const int tid  = threadIdx.x;
    const int warp = tid >> 5;
    const int lane = tid & 31;
    const int ul   = warp * 4 + (lane >> 3);   // local unit 0..63
    const int jg   = c * 64 + ul;              // global hidden unit
    const int kc   = lane & 7;                 // k-chunk 0..7 (32 h elems each)
    const bool leader = kc == 0;
    const int b0   = blockIdx.y * 2;

    // recurrent weights -> registers as f32x2 pairs, k base = kc*32
    u64 wr2[16], wz2[16], wn2[16];
    {
        const int k0 = kc * 32;
        const u64* pr = reinterpret_cast<const u64*>(Whh + (size_t)jg * HH + k0);
        const u64* pz = reinterpret_cast<const u64*>(Whh + (size_t)(256 + jg) * HH + k0);
        const u64* pq = reinterpret_cast<const u64*>(Whh + (size_t)(512 + jg) * HH + k0);
#pragma unroll
        for (int i = 0; i < 16; i++) { wr2[i] = pr[i]; wz2[i] = pz[i]; wn2[i] = pq[i]; }
    }
    float bhr = 0.f, bhz = 0.f, bhn = 0.f;
    if (leader) { bhr = bhh[jg]; bhz = bhh[256 + jg]; bhn = bhh[512 + jg]; }

    // zero parity-0 buffer (incl. padding — harmless)
    for (int i = tid; i < 2 * 8 * CPAD; i += 512) ((float*)hbuf[0])[i] = 0.f;
    const uint32_t mb = smem_u32(mbars);
    const uint32_t hb = smem_u32(hbuf);
    if (tid == 0) {
        asm volatile("mbarrier.init.shared.b64 [%0], 1;" :: "r"(mb)     : "memory");
        asm volatile("mbarrier.init.shared.b64 [%0], 1;" :: "r"(mb + 8) : "memory");
    }
    __syncthreads();
    asm volatile("barrier.cluster.arrive.aligned;" ::: "memory");
    asm volatile("barrier.cluster.wait.aligned;"   ::: "memory");

    // prefetch xg for t=0 (leaders)
    float xpr[2], xpz[2], xpn[2];
    if (leader) {
#pragma unroll
        for (int sb = 0; sb < 2; sb++) {
            size_t base = ((size_t)(b0 + sb) * SS) * G3;
            xpr[sb] = __ldg(&g_xg[base + jg]);
            xpz[sb] = __ldg(&g_xg[base + 256 + jg]);
            xpn[sb] = __ldg(&g_xg[base + 512 + jg]);
        }
    }

    // exchange-thread addressing (tid < 64): sb = tid>>5, pair idx = tid&31
    const int xsb = tid >> 5;
    const int xpi = tid & 31;
    // dest float offset (minus parity term): [sb][2c + (pi>>4)][(pi&15)*2]
    const uint32_t dst_off = (uint32_t)((((xsb * 8) + 2 * c + (xpi >> 4)) * CPAD
                                         + (xpi & 15) * 2) * 4);
    const uint32_t parity_stride = (uint32_t)(2 * 8 * CPAD * 4);
    // hold-state chunk for leaders (bug fixed: 2*c + (ul>>5), not ul>>5)
    const int hchunk = 2 * c + (ul >> 5);
    const int hoff   = ul & 31;

    int ph0 = 0, ph1 = 0;

    for (int t = 0; t < SS; t++) {
        const int p = t & 1, pq = p ^ 1;
        if (tid == 0) {
            // arm receive barrier for data landing in hbuf[pq]: 4 CTAs x 512B
            asm volatile("mbarrier.arrive.expect_tx.shared.b64 _, [%0], %1;"
                         :: "r"(mb + pq * 8), "r"(2048u) : "memory");
        }
        float xr[2], xz[2], xn[2];
        if (leader) {
#pragma unroll
            for (int sb = 0; sb < 2; sb++) { xr[sb]=xpr[sb]; xz[sb]=xpz[sb]; xn[sb]=xpn[sb]; }
            const int tn = (t + 1 < SS) ? t + 1 : t;
#pragma unroll
            for (int sb = 0; sb < 2; sb++) {
                size_t base = ((size_t)(b0 + sb) * SS + tn) * G3;
                xpr[sb] = __ldg(&g_xg[base + jg]);
                xpz[sb] = __ldg(&g_xg[base + 256 + jg]);
                xpn[sb] = __ldg(&g_xg[base + 512 + jg]);
            }
        }

#pragma unroll
        for (int sb = 0; sb < 2; sb++) {
            // conflict-free: lanes kc=0..7 start at banks 4*kc (+pad layout)
            const u64* hp = reinterpret_cast<const u64*>(&hbuf[p][sb][kc][0]);
            u64 aR = 0ull, aZ = 0ull, aN = 0ull;
#pragma unroll
            for (int i = 0; i < 16; i++) {
                u64 hv = hp[i];
                aR = ffma2(wr2[i], hv, aR);
                aZ = ffma2(wz2[i], hv, aZ);
                aN = ffma2(wn2[i], hv, aN);
            }
            float2 fR = unpack2(aR), fZ = unpack2(aZ), fN = unpack2(aN);
            float sR = fR.x + fR.y, sZ = fZ.x + fZ.y, sN = fN.x + fN.y;
#pragma unroll
            for (int d = 4; d; d >>= 1) {
                sR += __shfl_down_sync(0xffffffffu, sR, d);
                sZ += __shfl_down_sync(0xffffffffu, sZ, d);
                sN += __shfl_down_sync(0xffffffffu, sN, d);
            }
            if (leader) {
                float er = __expf(-(xr[sb] + sR + bhr));
                float r  = rcpa(1.f + er);
                float ez = __expf(-(xz[sb] + sZ + bhz));
                float z  = rcpa(1.f + ez);
                float na = xn[sb] + r * (sN + bhn);
                float en = __expf(-2.f * na);
                float n  = (1.f - en) * rcpa(1.f + en);
                float hold = hbuf[p][sb][hchunk][hoff];
                float hnew = n + z * (hold - n);
                out[((size_t)(b0 + sb) * SS + t) * ostride + jg] = hnew;
                stage[sb][ul] = hnew;
            }
        }
        __syncthreads();

        // exchange: 64 threads each push one 8B pair to all 4 ranks (st.async)
        if (tid < 64) {
            u64 v = *reinterpret_cast<const u64*>(&stage[xsb][2 * xpi]);
            uint32_t loff = hb + (uint32_t)pq * parity_stride + dst_off;
            uint32_t moff = mb + (uint32_t)(pq * 8);
#pragma unroll
            for (int r = 0; r < 4; r++) {
                uint32_t rh, rm;
                asm volatile("mapa.shared::cluster.u32 %0, %1, %2;" : "=r"(rh) : "r"(loff), "r"(r));
                asm volatile("mapa.shared::cluster.u32 %0, %1, %2;" : "=r"(rm) : "r"(moff), "r"(r));
                asm volatile("st.async.shared::cluster.mbarrier::complete_tx::bytes.b64 [%0], %1, [%2];"
                             :: "r"(rh), "l"(v), "r"(rm) : "memory");
            }
        }

        // wait for step t+1's h to fully land in our hbuf[pq]
        {
            uint32_t maddr = mb + pq * 8;
            uint32_t parity = pq ? ph1 : ph0;
            uint32_t done;
            asm volatile(
                "{\n\t.reg .pred p;\n\t"
                "mbarrier.try_wait.parity.acquire.cta.shared::cta.b64 p, [%1], %2;\n\t"
                "selp.b32 %0, 1, 0, p;\n\t}"
                : "=r"(done) : "r"(maddr), "r"(parity) : "memory");
            if (!done) {
                asm volatile(
                    "{\n\t.reg .pred P1;\n\t"
                    "WL_%=:\n\t"
                    "mbarrier.try_wait.parity.acquire.cta.shared::cta.b64 P1, [%0], %1, 0x989680;\n\t"
                    "@P1 bra.uni WD_%=;\n\t"
                    "bra.uni WL_%=;\n\t"
                    "WD_%=:\n\t}"
                    :: "r"(maddr), "r"(parity) : "memory");
            }
            if (pq) ph1 ^= 1; else ph0 ^= 1;
        }
    }
}

// ---------------------------------------------------------------------------
// h2 = concat[:, :, 256:512]  (vectorized copy)
// ---------------------------------------------------------------------------
__global__ void __launch_bounds__(256)
copy_h2_kernel(const float4* __restrict__ src, float4* __restrict__ dst)
{
    size_t i = (size_t)blockIdx.x * blockDim.x + threadIdx.x;
    size_t row = i >> 6;
    int col = (int)(i & 63);
    dst[row * 64 + col] = src[row * 128 + 64 + col];
}

// ---------------------------------------------------------------------------
extern "C" void kernel_launch(void* const* d_in, const int* in_sizes, int n_in,
                              void* d_out, int out_size)
{
    (void)in_sizes; (void)n_in; (void)out_size;
    const float* inputs = (const float*)d_in[0];
    const float* W_ih0  = (const float*)d_in[1];
    const float* W_hh0  = (const float*)d_in[2];
    const float* b_ih0  = (const float*)d_in[3];
    const float* b_hh0  = (const float*)d_in[4];
    const float* W_ih1  = (const float*)d_in[5];
    const float* W_hh1  = (const float*)d_in[6];
    const float* b_ih1  = (const float*)d_in[7];
    const float* b_hh1  = (const float*)d_in[8];

    float* out    = (float*)d_out;
    float* h2     = out;                               // [B,S,H]
    float* concat = out + (size_t)BB * SS * HH;        // [B,S,2H]

    dim3 gemm_grid(G3 / 64, (BB * SS) / 128);
    dim3 scan_grid(4, BB / 2);

    // Layer 0
    gemm_xg_kernel<<<gemm_grid, 256>>>(inputs, (long)II, W_ih0, b_ih0);
    gru_scan_kernel<<<scan_grid, 512>>>(W_hh0, b_hh0, concat, 2 * HH);

    // Layer 1 (reads h1 from concat, lda = 512)
    gemm_xg_kernel<<<gemm_grid, 256>>>(concat, (long)(2 * HH), W_ih1, b_ih1);
    gru_scan_kernel<<<scan_grid, 512>>>(W_hh1, b_hh1, concat + HH, 2 * HH);

    // h2 output = concat[:, :, 256:512]
    copy_h2_kernel<<<16384, 256>>>((const float4*)concat, (float4*)h2);
}